// round 9
// baseline (speedup 1.0000x reference)
#include <cuda_runtime.h>
#include <math_constants.h>
#include <stdint.h>

#define N_BINS  15
#define C_DIM   100
#define FULL    0xffffffffu
#define THREADS 256
#define BLOCKS  888          // 6 blocks/SM x 148 SMs -> one full wave

// Persistent accumulators. Zero at module load; the LAST block of every
// launch resets them after consuming -> deterministic across graph replays.
__device__ float    g_cnt[N_BINS];
__device__ double   g_conf[N_BINS];
__device__ float    g_accs[N_BINS];
__device__ unsigned g_ctr;

// Order-preserving float -> u32 map (u32 compare == float compare) + inverse.
__device__ __forceinline__ unsigned fmap(float f) {
    unsigned b = __float_as_uint(f);
    return ((int)b >= 0) ? (b | 0x80000000u) : ~b;
}
__device__ __forceinline__ float funmap(unsigned u) {
    unsigned b = (u & 0x80000000u) ? (u & 0x7fffffffu) : ~u;
    return __uint_as_float(b);
}

__global__ void __launch_bounds__(THREADS, 6) ece_fused_kernel(
    const float* __restrict__ logits,
    const void*  __restrict__ labels_raw,
    float* __restrict__ out,
    int n, int vec_ok, float inv_n)
{
    __shared__ float s_cnt[N_BINS], s_conf[N_BINS], s_acc[N_BINS];
    __shared__ int   s_is64;
    __shared__ unsigned s_ticket;

    const int tid  = threadIdx.x;
    const int lane = tid & 31;

    if (tid < N_BINS) { s_cnt[tid] = 0.f; s_conf[tid] = 0.f; s_acc[tid] = 0.f; }

    // Label dtype detect: odd int32 words all zero => int64 (little-endian).
    if (tid < 32) {
        int idx = 1 + 2 * tid;
        int v = (idx < n) ? ((const int*)labels_raw)[idx] : 0;
        unsigned any = __ballot_sync(FULL, v != 0);
        if (tid == 0) s_is64 = (any == 0) ? 1 : 0;
    }
    __syncthreads();

    const int is64 = s_is64;
    const int* __restrict__       lab32 = (const int*)labels_raw;
    const long long* __restrict__ lab64 = (const long long*)labels_raw;

    const int warp   = (int)((blockIdx.x * THREADS + tid) >> 5);
    const int nwarps = (BLOCKS * THREADS) >> 5;

    // Per-warp register histogram: lane b (b < 15) owns bin b.
    float r_cnt = 0.0f, r_conf = 0.0f, r_acc = 0.0f;

    if (vec_ok) {
        // pointer-increment addressing: one 64-bit add per row
        const float4* __restrict__ p =
            reinterpret_cast<const float4*>(logits) + (size_t)warp * 25 + lane;
        const size_t pstride = (size_t)nwarps * 25;

        int row = warp;
        float4 v = make_float4(0.f, 0.f, 0.f, 0.f);
        int lab = 0;
        if (row < n) {
            if (lane < 25) v = *p;
            lab = is64 ? (int)lab64[row] : lab32[row];
        }

        while (row < n) {
            const int next = row + nwarps;
            const float4* p2 = p + pstride;
            float4 v2 = make_float4(0.f, 0.f, 0.f, 0.f);
            int lab2 = 0;
            if (next < n) {                       // prefetch (depth-2 pipe)
                if (lane < 25) v2 = *p2;
                lab2 = is64 ? (int)lab64[next] : lab32[next];
            }

            // lane-local max: FMNMX tree (no index tracking)
            float m = (lane < 25)
                    ? fmaxf(fmaxf(v.x, v.y), fmaxf(v.z, v.w))
                    : -CUDART_INF_F;
            unsigned maxu = __reduce_max_sync(FULL, fmap(m));
            float mm = funmap(maxu);              // exact max logit

            // accuracy: does the label's position hold the max value?
            int lc = lab & 3;
            float vl = (lc == 0) ? v.x : (lc == 1) ? v.y
                     : (lc == 2) ? v.z : v.w;
            unsigned win = __ballot_sync(FULL, (lane == (lab >> 2)) && (vl == mm));

            // sigmoid monotone: conf = sigmoid(max logit)
            float conf = __fdividef(1.0f, 1.0f + __expf(-mm));
            // searchsorted(linspace(0,1,16), conf, 'left') - 1, clipped
            int bin = __float2int_ru(conf * 15.0f) - 1;
            bin = bin < 0 ? 0 : (bin > N_BINS - 1 ? N_BINS - 1 : bin);

            if (lane == bin) {
                r_cnt  += 1.0f;
                r_conf += conf;
                r_acc  += (win != 0u) ? 1.0f : 0.0f;
            }

            row = next; v = v2; lab = lab2; p = p2;
        }
    } else {
        for (int row = warp; row < n; row += nwarps) {
            float m = -CUDART_INF_F;
            float vl = 0.0f;
            int lab = is64 ? (int)lab64[row] : lab32[row];
            #pragma unroll
            for (int j = 0; j < 4; j++) {
                int c = lane + j * 32;
                if (c < C_DIM) {
                    float x = logits[(size_t)row * C_DIM + c];
                    m = fmaxf(m, x);
                    if (c == lab) vl = x;
                }
            }
            unsigned maxu = __reduce_max_sync(FULL, fmap(m));
            float mm = funmap(maxu);
            unsigned win = __ballot_sync(FULL,
                (lane == (lab & 31)) && (vl == mm));
            float conf = __fdividef(1.0f, 1.0f + __expf(-mm));
            int bin = __float2int_ru(conf * 15.0f) - 1;
            bin = bin < 0 ? 0 : (bin > N_BINS - 1 ? N_BINS - 1 : bin);
            if (lane == bin) {
                r_cnt += 1.0f; r_conf += conf;
                r_acc += (win != 0u) ? 1.0f : 0.0f;
            }
        }
    }

    // warp -> block (shared) -> global
    if (lane < N_BINS && r_cnt != 0.0f) {
        atomicAdd(&s_cnt[lane],  r_cnt);
        atomicAdd(&s_conf[lane], r_conf);
        atomicAdd(&s_acc[lane],  r_acc);
    }
    __syncthreads();
    if (tid < N_BINS) {
        float c = s_cnt[tid];
        if (c != 0.0f) {
            atomicAdd(&g_cnt[tid],  c);
            atomicAdd(&g_conf[tid], (double)s_conf[tid]);
            atomicAdd(&g_accs[tid], s_acc[tid]);
        }
    }

    // ticket: last block finalizes and resets persistent state
    __threadfence();
    if (tid == 0) s_ticket = atomicAdd(&g_ctr, 1u);
    __syncthreads();
    if (s_ticket == (unsigned)(gridDim.x - 1) && tid == 0) {
        __threadfence();
        float ece = 0.0f;
        #pragma unroll
        for (int b = 0; b < N_BINS; b++) {
            float cnt = g_cnt[b];
            if (cnt > 0.0f) {
                float avg_conf = (float)g_conf[b] / cnt;
                float avg_acc  = g_accs[b] / cnt;
                ece += (avg_conf - avg_acc) * (cnt * inv_n);
            }
            g_cnt[b] = 0.0f; g_conf[b] = 0.0; g_accs[b] = 0.0f;
        }
        out[0] = ece;
        g_ctr = 0u;
        __threadfence();
    }
}

extern "C" void kernel_launch(void* const* d_in, const int* in_sizes, int n_in,
                              void* d_out, int out_size) {
    // Resolve input order by element count (logits = C_DIM x labels count).
    long long s0 = in_sizes[0], s1 = in_sizes[1];
    int logits_idx = (s0 > s1) ? 0 : 1;
    int labels_idx = 1 - logits_idx;

    const float* logits     = (const float*)d_in[logits_idx];
    const void*  labels_raw = d_in[labels_idx];
    int n = (int)((s0 < s1) ? s0 : s1);
    float* out = (float*)d_out;

    int vec_ok = ((uintptr_t)logits & 15) == 0 ? 1 : 0;

    ece_fused_kernel<<<BLOCKS, THREADS>>>(logits, labels_raw, out, n, vec_ok,
                                          1.0f / (float)n);
}

// round 11
// speedup vs baseline: 1.6497x; 1.6497x over previous
#include <cuda_runtime.h>
#include <math_constants.h>
#include <stdint.h>

#define N_BINS  15
#define C_DIM   100
#define FULL    0xffffffffu
#define THREADS 256
#define BLOCKS  2368         // 8 blocks/SM: max warps -> max latency hiding

// Persistent accumulators. Zero at module load; the LAST block of every
// launch resets them after consuming -> deterministic across graph replays.
__device__ float    g_cnt[N_BINS];
__device__ double   g_conf[N_BINS];
__device__ float    g_accs[N_BINS];
__device__ unsigned g_ctr;

// Order-preserving float -> u32 map (u32 compare == float compare) + inverse.
__device__ __forceinline__ unsigned fmap(float f) {
    unsigned b = __float_as_uint(f);
    return ((int)b >= 0) ? (b | 0x80000000u) : ~b;
}
__device__ __forceinline__ float funmap(unsigned u) {
    unsigned b = (u & 0x80000000u) ? (u & 0x7fffffffu) : ~u;
    return __uint_as_float(b);
}

__global__ void __launch_bounds__(THREADS) ece_fused_kernel(
    const float* __restrict__ logits,
    const void*  __restrict__ labels_raw,
    float* __restrict__ out,
    int n, int vec_ok, float inv_n)
{
    __shared__ float s_cnt[N_BINS], s_conf[N_BINS], s_acc[N_BINS];
    __shared__ int   s_is64;
    __shared__ unsigned s_ticket;

    const int tid  = threadIdx.x;
    const int lane = tid & 31;

    if (tid < N_BINS) { s_cnt[tid] = 0.f; s_conf[tid] = 0.f; s_acc[tid] = 0.f; }

    // Label dtype detect: odd int32 words all zero => int64 (little-endian).
    if (tid < 32) {
        int idx = 1 + 2 * tid;
        int v = (idx < n) ? ((const int*)labels_raw)[idx] : 0;
        unsigned any = __ballot_sync(FULL, v != 0);
        if (tid == 0) s_is64 = (any == 0) ? 1 : 0;
    }
    __syncthreads();

    const int is64 = s_is64;
    const int* __restrict__       lab32 = (const int*)labels_raw;
    const long long* __restrict__ lab64 = (const long long*)labels_raw;

    const int warp   = (int)((blockIdx.x * THREADS + tid) >> 5);
    const int nwarps = (BLOCKS * THREADS) >> 5;

    // Per-warp register histogram: lane b (b < 15) owns bin b.
    float r_cnt = 0.0f, r_conf = 0.0f, r_acc = 0.0f;

    if (vec_ok) {
        // pointer-increment addressing: one 64-bit add per row
        const float4* __restrict__ p =
            reinterpret_cast<const float4*>(logits) + (size_t)warp * 25 + lane;
        const size_t pstride = (size_t)nwarps * 25;

        int row = warp;
        float4 v = make_float4(0.f, 0.f, 0.f, 0.f);
        int lab = 0;
        if (row < n) {
            if (lane < 25) v = *p;
            lab = is64 ? (int)lab64[row] : lab32[row];
        }

        while (row < n) {
            const int next = row + nwarps;
            const float4* p2 = p + pstride;
            float4 v2 = make_float4(0.f, 0.f, 0.f, 0.f);
            int lab2 = 0;
            if (next < n) {                       // prefetch (depth-2 pipe)
                if (lane < 25) v2 = *p2;
                lab2 = is64 ? (int)lab64[next] : lab32[next];
            }

            // lane-local max: FMNMX tree (no index tracking)
            float m = (lane < 25)
                    ? fmaxf(fmaxf(v.x, v.y), fmaxf(v.z, v.w))
                    : -CUDART_INF_F;
            unsigned maxu = __reduce_max_sync(FULL, fmap(m));
            float mm = funmap(maxu);              // exact max logit

            // accuracy: does the label's position hold the max value?
            int lc = lab & 3;
            float vl = (lc == 0) ? v.x : (lc == 1) ? v.y
                     : (lc == 2) ? v.z : v.w;
            unsigned win = __ballot_sync(FULL, (lane == (lab >> 2)) && (vl == mm));

            // sigmoid monotone: conf = sigmoid(max logit)
            float conf = __fdividef(1.0f, 1.0f + __expf(-mm));
            // searchsorted(linspace(0,1,16), conf, 'left') - 1, clipped
            int bin = __float2int_ru(conf * 15.0f) - 1;
            bin = bin < 0 ? 0 : (bin > N_BINS - 1 ? N_BINS - 1 : bin);

            if (lane == bin) {
                r_cnt  += 1.0f;
                r_conf += conf;
                r_acc  += (win != 0u) ? 1.0f : 0.0f;
            }

            row = next; v = v2; lab = lab2; p = p2;
        }
    } else {
        for (int row = warp; row < n; row += nwarps) {
            float m = -CUDART_INF_F;
            float vl = 0.0f;
            int lab = is64 ? (int)lab64[row] : lab32[row];
            #pragma unroll
            for (int j = 0; j < 4; j++) {
                int c = lane + j * 32;
                if (c < C_DIM) {
                    float x = logits[(size_t)row * C_DIM + c];
                    m = fmaxf(m, x);
                    if (c == lab) vl = x;
                }
            }
            unsigned maxu = __reduce_max_sync(FULL, fmap(m));
            float mm = funmap(maxu);
            unsigned win = __ballot_sync(FULL,
                (lane == (lab & 31)) && (vl == mm));
            float conf = __fdividef(1.0f, 1.0f + __expf(-mm));
            int bin = __float2int_ru(conf * 15.0f) - 1;
            bin = bin < 0 ? 0 : (bin > N_BINS - 1 ? N_BINS - 1 : bin);
            if (lane == bin) {
                r_cnt += 1.0f; r_conf += conf;
                r_acc += (win != 0u) ? 1.0f : 0.0f;
            }
        }
    }

    // warp -> block (shared) -> global
    if (lane < N_BINS && r_cnt != 0.0f) {
        atomicAdd(&s_cnt[lane],  r_cnt);
        atomicAdd(&s_conf[lane], r_conf);
        atomicAdd(&s_acc[lane],  r_acc);
    }
    __syncthreads();
    if (tid < N_BINS) {
        float c = s_cnt[tid];
        if (c != 0.0f) {
            atomicAdd(&g_cnt[tid],  c);
            atomicAdd(&g_conf[tid], (double)s_conf[tid]);
            atomicAdd(&g_accs[tid], s_acc[tid]);
        }
    }

    // ticket: last block finalizes and resets persistent state
    __threadfence();
    if (tid == 0) s_ticket = atomicAdd(&g_ctr, 1u);
    __syncthreads();
    if (s_ticket == (unsigned)(gridDim.x - 1) && tid == 0) {
        __threadfence();
        float ece = 0.0f;
        #pragma unroll
        for (int b = 0; b < N_BINS; b++) {
            float cnt = g_cnt[b];
            if (cnt > 0.0f) {
                float avg_conf = (float)g_conf[b] / cnt;
                float avg_acc  = g_accs[b] / cnt;
                ece += (avg_conf - avg_acc) * (cnt * inv_n);
            }
            g_cnt[b] = 0.0f; g_conf[b] = 0.0; g_accs[b] = 0.0f;
        }
        out[0] = ece;
        g_ctr = 0u;
        __threadfence();
    }
}

extern "C" void kernel_launch(void* const* d_in, const int* in_sizes, int n_in,
                              void* d_out, int out_size) {
    // Resolve input order by element count (logits = C_DIM x labels count).
    long long s0 = in_sizes[0], s1 = in_sizes[1];
    int logits_idx = (s0 > s1) ? 0 : 1;
    int labels_idx = 1 - logits_idx;

    const float* logits     = (const float*)d_in[logits_idx];
    const void*  labels_raw = d_in[labels_idx];
    int n = (int)((s0 < s1) ? s0 : s1);
    float* out = (float*)d_out;

    int vec_ok = ((uintptr_t)logits & 15) == 0 ? 1 : 0;

    ece_fused_kernel<<<BLOCKS, THREADS>>>(logits, labels_raw, out, n, vec_ok,
                                          1.0f / (float)n);
}

// round 12
// speedup vs baseline: 2.0391x; 1.2361x over previous
#include <cuda_runtime.h>
#include <math_constants.h>
#include <stdint.h>

#define N_BINS  15
#define C_DIM   100
#define FULL    0xffffffffu
#define THREADS 256
#define BLOCKS  2368         // 8 blocks/SM: max warps resident

// Persistent accumulators. Zero at module load; the LAST block of every
// launch resets them after consuming -> deterministic across graph replays.
__device__ float    g_cnt[N_BINS];
__device__ double   g_conf[N_BINS];
__device__ float    g_accs[N_BINS];
__device__ unsigned g_ctr;

// Order-preserving float -> u32 map (u32 compare == float compare) + inverse.
__device__ __forceinline__ unsigned fmap(float f) {
    unsigned b = __float_as_uint(f);
    return ((int)b >= 0) ? (b | 0x80000000u) : ~b;
}
__device__ __forceinline__ float funmap(unsigned u) {
    unsigned b = (u & 0x80000000u) ? (u & 0x7fffffffu) : ~u;
    return __uint_as_float(b);
}

__global__ void __launch_bounds__(THREADS) ece_fused_kernel(
    const float* __restrict__ logits,
    const char*  __restrict__ labels_raw,
    float* __restrict__ out,
    int n, int vec_ok, float inv_n)
{
    __shared__ float s_cnt[N_BINS], s_conf[N_BINS], s_acc[N_BINS];
    __shared__ int   s_lstride;
    __shared__ unsigned s_ticket;

    const int tid  = threadIdx.x;
    const int lane = tid & 31;

    if (tid < N_BINS) { s_cnt[tid] = 0.f; s_conf[tid] = 0.f; s_acc[tid] = 0.f; }

    // Label dtype detect: odd int32 words all zero => int64 (little-endian).
    // Either way the label value is the 32-bit word at row*lstride.
    if (tid < 32) {
        int idx = 1 + 2 * tid;
        int v = (idx < n) ? ((const int*)labels_raw)[idx] : 0;
        unsigned any = __ballot_sync(FULL, v != 0);
        if (tid == 0) s_lstride = (any == 0) ? 8 : 4;
    }
    __syncthreads();

    const size_t lstride = (size_t)s_lstride;

    const int warp   = (int)((blockIdx.x * THREADS + tid) >> 5);
    const int nwarps = (BLOCKS * THREADS) >> 5;

    // Per-warp register histogram: lane b (b < 15) owns bin b.
    float r_cnt = 0.0f, r_conf = 0.0f, r_acc = 0.0f;

    if (vec_ok && warp < n) {
        const int lcl = lane < 25 ? lane : 24;    // clamp: dup loads coalesce
        const float4* __restrict__ p =
            reinterpret_cast<const float4*>(logits) + (size_t)warp * 25 + lcl;
        const char* __restrict__ lp = labels_raw + (size_t)warp * lstride;
        const size_t pstride = (size_t)nwarps * 25;
        const size_t lstep   = (size_t)nwarps * lstride;

        const int nrows = (n - 1 - warp) / nwarps + 1;

        float4 v  = *p;
        int    lab = *(const int*)lp;

        #pragma unroll 2
        for (int it = 0; it < nrows - 1; it++) {
            p  += pstride;                         // prefetch next row
            lp += lstep;
            const float4 v2  = *p;
            const int    lab2 = *(const int*)lp;

            // ---- process current row ----
            float m = fmaxf(fmaxf(v.x, v.y), fmaxf(v.z, v.w));
            unsigned maxu = __reduce_max_sync(FULL, fmap(m));
            float mm = funmap(maxu);               // exact max logit

            int lc = lab & 3;
            float vl = (lc == 0) ? v.x : (lc == 1) ? v.y
                     : (lc == 2) ? v.z : v.w;
            unsigned win = __ballot_sync(FULL,
                (lane == (lab >> 2)) && (vl == mm));

            float conf = __fdividef(1.0f, 1.0f + __expf(-mm));
            int bin = __float2int_ru(conf * 15.0f) - 1;
            bin = bin < 0 ? 0 : (bin > N_BINS - 1 ? N_BINS - 1 : bin);
            if (lane == bin) {
                r_cnt  += 1.0f;
                r_conf += conf;
                r_acc  += (win != 0u) ? 1.0f : 0.0f;
            }

            v = v2; lab = lab2;
        }
        // ---- last row (no prefetch) ----
        {
            float m = fmaxf(fmaxf(v.x, v.y), fmaxf(v.z, v.w));
            unsigned maxu = __reduce_max_sync(FULL, fmap(m));
            float mm = funmap(maxu);
            int lc = lab & 3;
            float vl = (lc == 0) ? v.x : (lc == 1) ? v.y
                     : (lc == 2) ? v.z : v.w;
            unsigned win = __ballot_sync(FULL,
                (lane == (lab >> 2)) && (vl == mm));
            float conf = __fdividef(1.0f, 1.0f + __expf(-mm));
            int bin = __float2int_ru(conf * 15.0f) - 1;
            bin = bin < 0 ? 0 : (bin > N_BINS - 1 ? N_BINS - 1 : bin);
            if (lane == bin) {
                r_cnt  += 1.0f;
                r_conf += conf;
                r_acc  += (win != 0u) ? 1.0f : 0.0f;
            }
        }
    } else if (warp < n) {
        // scalar fallback (unaligned logits base)
        for (int row = warp; row < n; row += nwarps) {
            float m = -CUDART_INF_F;
            float vl = 0.0f;
            int lab = *(const int*)(labels_raw + (size_t)row * lstride);
            #pragma unroll
            for (int j = 0; j < 4; j++) {
                int c = lane + j * 32;
                if (c < C_DIM) {
                    float x = logits[(size_t)row * C_DIM + c];
                    m = fmaxf(m, x);
                    if (c == lab) vl = x;
                }
            }
            unsigned maxu = __reduce_max_sync(FULL, fmap(m));
            float mm = funmap(maxu);
            unsigned win = __ballot_sync(FULL,
                (lane == (lab & 31)) && (vl == mm));
            float conf = __fdividef(1.0f, 1.0f + __expf(-mm));
            int bin = __float2int_ru(conf * 15.0f) - 1;
            bin = bin < 0 ? 0 : (bin > N_BINS - 1 ? N_BINS - 1 : bin);
            if (lane == bin) {
                r_cnt += 1.0f; r_conf += conf;
                r_acc += (win != 0u) ? 1.0f : 0.0f;
            }
        }
    }

    // warp -> block (shared) -> global
    if (lane < N_BINS && r_cnt != 0.0f) {
        atomicAdd(&s_cnt[lane],  r_cnt);
        atomicAdd(&s_conf[lane], r_conf);
        atomicAdd(&s_acc[lane],  r_acc);
    }
    __syncthreads();
    if (tid < N_BINS) {
        float c = s_cnt[tid];
        if (c != 0.0f) {
            atomicAdd(&g_cnt[tid],  c);
            atomicAdd(&g_conf[tid], (double)s_conf[tid]);
            atomicAdd(&g_accs[tid], s_acc[tid]);
        }
    }

    // ticket: last block finalizes and resets persistent state
    __threadfence();
    if (tid == 0) s_ticket = atomicAdd(&g_ctr, 1u);
    __syncthreads();
    if (s_ticket == (unsigned)(gridDim.x - 1) && tid == 0) {
        __threadfence();
        float ece = 0.0f;
        #pragma unroll
        for (int b = 0; b < N_BINS; b++) {
            float cnt = g_cnt[b];
            if (cnt > 0.0f) {
                float avg_conf = (float)g_conf[b] / cnt;
                float avg_acc  = g_accs[b] / cnt;
                ece += (avg_conf - avg_acc) * (cnt * inv_n);
            }
            g_cnt[b] = 0.0f; g_conf[b] = 0.0; g_accs[b] = 0.0f;
        }
        out[0] = ece;
        g_ctr = 0u;
        __threadfence();
    }
}

extern "C" void kernel_launch(void* const* d_in, const int* in_sizes, int n_in,
                              void* d_out, int out_size) {
    // Resolve input order by element count (logits = C_DIM x labels count).
    long long s0 = in_sizes[0], s1 = in_sizes[1];
    int logits_idx = (s0 > s1) ? 0 : 1;
    int labels_idx = 1 - logits_idx;

    const float* logits     = (const float*)d_in[logits_idx];
    const char*  labels_raw = (const char*)d_in[labels_idx];
    int n = (int)((s0 < s1) ? s0 : s1);
    float* out = (float*)d_out;

    int vec_ok = ((uintptr_t)logits & 15) == 0 ? 1 : 0;

    ece_fused_kernel<<<BLOCKS, THREADS>>>(logits, labels_raw, out, n, vec_ok,
                                          1.0f / (float)n);
}